// round 13
// baseline (speedup 1.0000x reference)
#include <cuda_runtime.h>
#include <cuda_fp16.h>
#include <math.h>
#include <stdint.h>

// Problem constants: B=8, L=1024, D=1024, F=4096, nh=8, hs=128, M=B*L=8192

// fp16 scratch
__device__ __half g_scores[67108864];  // 64*1024*1024  S (fp16, incl. Srel)
__device__ __half g_qer[67108864];     // 64*1024*1024  QEr (fp16)
__device__ __half g_ln[8388608];       // LN output
__device__ __half g_qkv[25165824];     // QKV
__device__ __half g_p[67108864];       // softmax P
__device__ __half g_y[8388608];        // attn out
__device__ __half g_hh[33554432];      // MLP hidden
__device__ __half g_wq[3145728];       // W_qkv^T  (3072 x 1024)
__device__ __half g_wo[1048576];       // W_o^T    (1024 x 1024)
__device__ __half g_wf[4194304];       // W_fc^T   (4096 x 1024)
__device__ __half g_wp[4194304];       // W_proj^T (1024 x 4096)
__device__ __half g_vt[8388608];       // v^T per head (64 x 128 x 1024)
__device__ __half g_er[131072];        // Er (1024 x 128)

__device__ __forceinline__ uint32_t smem_u32(const void* p) {
    uint32_t a;
    asm("{ .reg .u64 t; cvta.to.shared.u64 t, %1; cvt.u32.u64 %0, t; }" : "=r"(a) : "l"(p));
    return a;
}
__device__ __forceinline__ void cpa16(uint32_t dst, const void* src) {
    asm volatile("cp.async.cg.shared.global [%0], [%1], 16;\n" :: "r"(dst), "l"(src));
}
#define CPA_COMMIT() asm volatile("cp.async.commit_group;\n" ::: "memory")
#define CPA_WAIT2()  asm volatile("cp.async.wait_group 2;\n" ::: "memory")

__device__ __forceinline__ void ldsm4(uint32_t& r0, uint32_t& r1, uint32_t& r2, uint32_t& r3,
                                      uint32_t addr) {
    asm volatile("ldmatrix.sync.aligned.m8n8.x4.shared.b16 {%0,%1,%2,%3}, [%4];"
                 : "=r"(r0), "=r"(r1), "=r"(r2), "=r"(r3) : "r"(addr));
}
__device__ __forceinline__ void mma_f16(float c[4], const uint32_t a[4],
                                        uint32_t b0, uint32_t b1) {
    asm volatile(
        "mma.sync.aligned.m16n8k16.row.col.f32.f16.f16.f32 "
        "{%0,%1,%2,%3}, {%4,%5,%6,%7}, {%8,%9}, {%0,%1,%2,%3};"
        : "+f"(c[0]), "+f"(c[1]), "+f"(c[2]), "+f"(c[3])
        : "r"(a[0]), "r"(a[1]), "r"(a[2]), "r"(a[3]), "r"(b0), "r"(b1));
}

// ---------------------------------------------------------------------------
// fp16 mma.sync GEMM: C[MxN] = A[MxK] * Bt[NxK]^T, A/Bt fp16 K-major.
// Block tile 128x128, k-step 32, 4-stage cp.async (wait_group 2).
// 8 warps (2m x 4n), warp tile 64x32, 2 CTAs/SM.
// Batched via blockIdx.z: hi=z>>3, lo=z&7.
// epilogue: 0=none, 1=+bias, 2=+bias+GELU, 3=+bias+residual(fp32),
//           4=+skewed rel bias via smem-staged band:
//             C[r][cb] += Eh[r][cb - r + 1023] (Eh fp16 = resid arg, same ldc)
// tri: 0=full, 1=lower-tri skip, 2=anti-tri skip, 3=causal K bound
// half_out: 1 -> C is __half, else float
// ---------------------------------------------------------------------------
__global__ void __launch_bounds__(256, 2)
gemm_f16(const __half* __restrict__ A, int lda, long long sAhi, long long sAlo,
         const __half* __restrict__ Bt, int ldb, long long sBhi, long long sBlo,
         void* __restrict__ Cv, int ldc, long long sChi, long long sClo,
         int N, int K,
         const float* __restrict__ bias, const void* __restrict__ resid,
         int epilogue, int tri, int half_out)
{
    const int n0 = blockIdx.x * 128;
    const int m0 = blockIdx.y * 128;
    if (tri == 1 && n0 > m0) return;
    if (tri == 2 && (m0 + n0) < (N - 255)) return;
    const int kmax = (tri == 3) ? min(K, m0 + 128) : K;
    const int ns = kmax >> 5;   // k-tiles of 32 (>= 4 for all calls)

    const int z = blockIdx.z, hi = z >> 3, lo = z & 7;
    A  += hi * sAhi + lo * sAlo;
    Bt += hi * sBhi + lo * sBlo;
    const long long coff = hi * sChi + lo * sClo;

    extern __shared__ __align__(16) char smem[];
    const uint32_t sbase = smem_u32(smem);

    const int tid  = threadIdx.x;
    const int lane = tid & 31;
    const int warp = tid >> 5;
    const int g  = lane >> 2;
    const int tg = lane & 3;
    const int wm = (warp >> 2) * 64;
    const int wn = (warp & 3) * 32;

    // staging: row = tid>>1 (0..127), chunks c0=(tid&1)*2, c0+1 (16B of 8 halves)
    const int srow = tid >> 1;
    const int c0   = (tid & 1) * 2;
    const uint32_t dA = (uint32_t)(srow * 80 + c0 * 16);
    const __half* Ap = A + (size_t)(m0 + srow) * lda + c0 * 8;
    const __half* Bp = Bt + (size_t)(n0 + srow) * ldb + c0 * 8;

    // ldmatrix lane addresses
    const uint32_t lmA = sbase +         (uint32_t)((wm + (lane & 15)) * 80 + (lane >> 4) * 16);
    const uint32_t lmB = sbase + 10240 + (uint32_t)((wn + (lane & 15)) * 80 + (lane >> 4) * 16);

#define STAGE(s_, p_) do { \
        const uint32_t bb_ = sbase + (uint32_t)(p_) * 20480u; \
        const __half* ga_ = Ap + ((s_) << 5); \
        const __half* gb_ = Bp + ((s_) << 5); \
        cpa16(bb_ + dA, ga_); \
        cpa16(bb_ + dA + 16, ga_ + 8); \
        cpa16(bb_ + 10240 + dA, gb_); \
        cpa16(bb_ + 10240 + dA + 16, gb_ + 8); \
    } while (0)

    float acc[4][4][4] = {};

    STAGE(0, 0); CPA_COMMIT();
    STAGE(1, 1); CPA_COMMIT();
    STAGE(2, 2); CPA_COMMIT();

    int p = 0;
    for (int s = 0; s < ns; s++) {
        CPA_WAIT2();
        __syncthreads();
        const uint32_t pb = (uint32_t)p * 20480u;
#pragma unroll
        for (int k16 = 0; k16 < 2; k16++) {
            uint32_t af[4][4], bf[4][2];
#pragma unroll
            for (int mt = 0; mt < 4; mt++)
                ldsm4(af[mt][0], af[mt][1], af[mt][2], af[mt][3],
                      lmA + pb + mt * 1280u + k16 * 32u);
#pragma unroll
            for (int ntp = 0; ntp < 2; ntp++)
                ldsm4(bf[ntp * 2][0], bf[ntp * 2 + 1][0], bf[ntp * 2][1], bf[ntp * 2 + 1][1],
                      lmB + pb + ntp * 1280u + k16 * 32u);
#pragma unroll
            for (int mt = 0; mt < 4; mt++)
#pragma unroll
                for (int nt = 0; nt < 4; nt++)
                    mma_f16(acc[mt][nt], af[mt], bf[nt][0], bf[nt][1]);
        }
        if (s + 3 < ns) {
            STAGE(s + 3, (p + 3) & 3);
        }
        CPA_COMMIT();
        p = (p + 1) & 3;
    }

    // --- epilogue==4: stage the 128x256 skew band into smem (coalesced) ---
    // band[rr][idx] holds Eh[m0+rr][jb + idx], jb = n0 - m0 + 896 (>=0, 8-aligned).
    // j > 1023 region is causally masked; clamp chunk start to 1016 to stay in-bounds.
    __half* band = (__half*)smem;
    if (epilogue == 4) {
        __syncthreads();                 // mainloop smem no longer needed
        const int jb = n0 - m0 + 896;
        const __half* Eh = (const __half*)resid;
        for (int c = tid; c < 4096; c += 256) {      // 128 rows x 32 chunks of 8 halves
            const int rr = c >> 5, ch = c & 31;
            int j0 = jb + ch * 8;
            if (j0 > 1016) j0 = 1016;
            const float4 v = *(const float4*)(Eh + (size_t)coff + (size_t)(m0 + rr) * ldc + j0);
            *(float4*)&band[rr * 264 + ch * 8] = v;
        }
        __syncthreads();
    }

    // Epilogue: acc[mt][nt] -> rows (r, r+8), cols (cb, cb+1)
#pragma unroll
    for (int mt = 0; mt < 4; mt++) {
#pragma unroll
        for (int nt = 0; nt < 4; nt++) {
            const int r  = m0 + wm + mt * 16 + g;
            const int cb = n0 + wn + nt * 8 + tg * 2;
            float b0 = 0.f, b1 = 0.f;
            if (epilogue == 1 || epilogue == 2 || epilogue == 3) {
                b0 = bias[cb]; b1 = bias[cb + 1];
            }
            float o00 = acc[mt][nt][0] + b0, o01 = acc[mt][nt][1] + b1;
            float o10 = acc[mt][nt][2] + b0, o11 = acc[mt][nt][3] + b1;
            const size_t i0 = (size_t)coff + (size_t)r * ldc + cb;
            const size_t i1 = (size_t)coff + (size_t)(r + 8) * ldc + cb;
            if (epilogue == 2) {
                o00 *= normcdff(o00); o01 *= normcdff(o01);
                o10 *= normcdff(o10); o11 *= normcdff(o11);
            } else if (epilogue == 3) {
                const float* rf = (const float*)resid;
                const float2 r0 = *(const float2*)(rf + i0);
                const float2 r1 = *(const float2*)(rf + i1);
                o00 += r0.x; o01 += r0.y; o10 += r1.x; o11 += r1.y;
            } else if (epilogue == 4) {
                // idx = (cb-n0) - (r-m0) + 127 in [0,254]
                const int rr0 = wm + mt * 16 + g;
                const int cc  = wn + nt * 8 + tg * 2;
                const int ix0 = rr0 * 264 + cc - rr0 + 127;
                const int rr1 = rr0 + 8;
                const int ix1 = rr1 * 264 + cc - rr1 + 127;
                o00 += __half2float(band[ix0]);     o01 += __half2float(band[ix0 + 1]);
                o10 += __half2float(band[ix1]);     o11 += __half2float(band[ix1 + 1]);
            }
            if (half_out) {
                *(__half2*)((__half*)Cv + i0) = __floats2half2_rn(o00, o01);
                *(__half2*)((__half*)Cv + i1) = __floats2half2_rn(o10, o11);
            } else {
                *(float2*)((float*)Cv + i0) = make_float2(o00, o01);
                *(float2*)((float*)Cv + i1) = make_float2(o10, o11);
            }
        }
    }
#undef STAGE
}

// ---------------------------------------------------------------------------
// Transpose fp32 -> fp16, coalesced __half2 writes.
// grid: (in_cols/32, in_rows/64), block (32, 8)
// ---------------------------------------------------------------------------
__global__ void __launch_bounds__(256)
transpose_f2h(const float* __restrict__ in, int ldi,
              __half* __restrict__ out, int ldo)
{
    __shared__ float t[64][33];
    const int c0 = blockIdx.x * 32, r0 = blockIdx.y * 64;
    const int x = threadIdx.x, y = threadIdx.y;
#pragma unroll
    for (int i = 0; i < 64; i += 8)
        t[y + i][x] = in[(size_t)(r0 + y + i) * ldi + c0 + x];
    __syncthreads();
#pragma unroll
    for (int i = 0; i < 32; i += 8) {
        const int orow = c0 + y + i;
        const __half2 v = __floats2half2_rn(t[2 * x][y + i], t[2 * x + 1][y + i]);
        *(__half2*)(out + (size_t)orow * ldo + r0 + 2 * x) = v;
    }
}

// Transpose fp16 -> fp16 (batched, for vT), coalesced __half2 writes.
__global__ void __launch_bounds__(256)
transpose_h2h(const __half* __restrict__ in, long long sIhi, long long sIlo, int ldi,
              __half* __restrict__ out, long long sOhi, long long sOlo, int ldo)
{
    __shared__ __half t[64][33];
    const int z = blockIdx.z, hi = z >> 3, lo = z & 7;
    in  += hi * sIhi + lo * sIlo;
    out += hi * sOhi + lo * sOlo;
    const int c0 = blockIdx.x * 32, r0 = blockIdx.y * 64;
    const int x = threadIdx.x, y = threadIdx.y;
#pragma unroll
    for (int i = 0; i < 64; i += 8)
        t[y + i][x] = in[(size_t)(r0 + y + i) * ldi + c0 + x];
    __syncthreads();
#pragma unroll
    for (int i = 0; i < 32; i += 8) {
        const int orow = c0 + y + i;
        __half2 v;
        v.x = t[2 * x][y + i];
        v.y = t[2 * x + 1][y + i];
        *(__half2*)(out + (size_t)orow * ldo + r0 + 2 * x) = v;
    }
}

__global__ void __launch_bounds__(256)
copy_f2h(const float4* __restrict__ in, __half* __restrict__ out, int n4)
{
    const int i = blockIdx.x * 256 + threadIdx.x;
    if (i < n4) {
        const float4 v = in[i];
        *(__half2*)(out + i * 4)     = __floats2half2_rn(v.x, v.y);
        *(__half2*)(out + i * 4 + 2) = __floats2half2_rn(v.z, v.w);
    }
}

// ---------------------------------------------------------------------------
// LayerNorm (rows of 1024), fp32 in -> fp16 out.
// ---------------------------------------------------------------------------
__global__ void __launch_bounds__(256)
ln_kernel(const float* __restrict__ x, const float* __restrict__ g,
          const float* __restrict__ b, __half* __restrict__ out)
{
    const int row = blockIdx.x;
    const int tid = threadIdx.x;
    const float4 xv = ((const float4*)(x + (size_t)row * 1024))[tid];

    float s  = xv.x + xv.y + xv.z + xv.w;
    float ss = xv.x * xv.x + xv.y * xv.y + xv.z * xv.z + xv.w * xv.w;
#pragma unroll
    for (int o = 16; o; o >>= 1) {
        s  += __shfl_xor_sync(0xffffffffu, s, o);
        ss += __shfl_xor_sync(0xffffffffu, ss, o);
    }
    __shared__ float sm[16];
    if ((tid & 31) == 0) { sm[tid >> 5] = s; sm[8 + (tid >> 5)] = ss; }
    __syncthreads();
    float S = 0.f, SS = 0.f;
#pragma unroll
    for (int i = 0; i < 8; i++) { S += sm[i]; SS += sm[8 + i]; }
    const float mu  = S * (1.f / 1024.f);
    const float var = SS * (1.f / 1024.f) - mu * mu;
    const float rs  = rsqrtf(var + 1e-5f);

    const float4 gv = ((const float4*)g)[tid];
    const float4 bv = ((const float4*)b)[tid];
    __half* orow = out + (size_t)row * 1024 + tid * 4;
    *(__half2*)(orow)     = __floats2half2_rn((xv.x - mu) * rs * gv.x + bv.x,
                                              (xv.y - mu) * rs * gv.y + bv.y);
    *(__half2*)(orow + 2) = __floats2half2_rn((xv.z - mu) * rs * gv.z + bv.z,
                                              (xv.w - mu) * rs * gv.w + bv.w);
}

// ---------------------------------------------------------------------------
// Causal softmax: S (fp16, incl. skewed rel bias) -> P fp16, half2 I/O.
// Each thread handles k = 2*tid + i*512, i in {0,1}.
// Writes only up to the causal tile boundary kend = round_up(q+1, 128) (even).
// ---------------------------------------------------------------------------
__global__ void __launch_bounds__(256)
softmax_kernel(const __half* __restrict__ S, __half* __restrict__ P)
{
    const int q  = blockIdx.x;
    const int bh = blockIdx.y;
    const size_t base = ((size_t)bh * 1024 + q) * 1024;
    const int tid = threadIdx.x;
    const float scale = 0.08838834764831845f;  // 1/sqrt(128)
    const int kend = ((q >> 7) + 1) << 7;

    float v[4];
    float mx = -3.4e38f;
#pragma unroll
    for (int i = 0; i < 2; i++) {
        const int k2 = tid * 2 + i * 512;
        const __half2 h = *(const __half2*)(S + base + k2);
        const float2 f = __half22float2(h);
        const float v0 = (k2     <= q) ? f.x * scale : -3.4e38f;
        const float v1 = (k2 + 1 <= q) ? f.y * scale : -3.4e38f;
        v[i * 2]     = v0;
        v[i * 2 + 1] = v1;
        mx = fmaxf(mx, fmaxf(v0, v1));
    }
#pragma unroll
    for (int o = 16; o; o >>= 1) mx = fmaxf(mx, __shfl_xor_sync(0xffffffffu, mx, o));
    __shared__ float red[8];
    if ((tid & 31) == 0) red[tid >> 5] = mx;
    __syncthreads();
    float m2 = red[0];
#pragma unroll
    for (int i = 1; i < 8; i++) m2 = fmaxf(m2, red[i]);
    __syncthreads();

    float sum = 0.f;
#pragma unroll
    for (int i = 0; i < 4; i++) {
        const float e = (v[i] > -1e37f) ? expf(v[i] - m2) : 0.f;
        v[i] = e;
        sum += e;
    }
#pragma unroll
    for (int o = 16; o; o >>= 1) sum += __shfl_xor_sync(0xffffffffu, sum, o);
    if ((tid & 31) == 0) red[tid >> 5] = sum;
    __syncthreads();
    float tot = 0.f;
#pragma unroll
    for (int i = 0; i < 8; i++) tot += red[i];
    const float inv = 1.f / tot;
#pragma unroll
    for (int i = 0; i < 2; i++) {
        const int k2 = tid * 2 + i * 512;
        if (k2 < kend) {
            *(__half2*)(P + base + k2) =
                __floats2half2_rn(v[i * 2] * inv, v[i * 2 + 1] * inv);
        }
    }
}

// ---------------------------------------------------------------------------
extern "C" void kernel_launch(void* const* d_in, const int* in_sizes, int n_in,
                              void* d_out, int out_size)
{
    (void)in_sizes; (void)n_in; (void)out_size;
    const float* x      = (const float*)d_in[0];
    const float* W_qkv  = (const float*)d_in[1];
    const float* b_qkv  = (const float*)d_in[2];
    const float* W_o    = (const float*)d_in[3];
    const float* b_o    = (const float*)d_in[4];
    const float* Er     = (const float*)d_in[5];
    const float* ln1_g  = (const float*)d_in[6];
    const float* ln1_b  = (const float*)d_in[7];
    const float* ln2_g  = (const float*)d_in[8];
    const float* ln2_b  = (const float*)d_in[9];
    const float* W_fc   = (const float*)d_in[10];
    const float* b_fc   = (const float*)d_in[11];
    const float* W_proj = (const float*)d_in[12];
    const float* b_proj = (const float*)d_in[13];
    float* out = (float*)d_out;

    __half *sc, *qer, *ln, *qkv, *pb, *yb, *hb, *wq, *wo, *wf, *wp, *vt, *er;
    cudaGetSymbolAddress((void**)&sc,  g_scores);
    cudaGetSymbolAddress((void**)&qer, g_qer);
    cudaGetSymbolAddress((void**)&ln,  g_ln);
    cudaGetSymbolAddress((void**)&qkv, g_qkv);
    cudaGetSymbolAddress((void**)&pb,  g_p);
    cudaGetSymbolAddress((void**)&yb,  g_y);
    cudaGetSymbolAddress((void**)&hb,  g_hh);
    cudaGetSymbolAddress((void**)&wq,  g_wq);
    cudaGetSymbolAddress((void**)&wo,  g_wo);
    cudaGetSymbolAddress((void**)&wf,  g_wf);
    cudaGetSymbolAddress((void**)&wp,  g_wp);
    cudaGetSymbolAddress((void**)&vt,  g_vt);
    cudaGetSymbolAddress((void**)&er,  g_er);

    const int SMEM_DYN = 4 * 20480;   // 80 KB, 4 stages (also holds skew band)
    cudaFuncSetAttribute(gemm_f16, cudaFuncAttributeMaxDynamicSharedMemorySize, SMEM_DYN);

    const long long sq_hi = 1024LL * 3072;      // per-b stride in qkv (halves)
    const long long sq_lo = 128LL;               // per-head stride in qkv
    const long long ss_hi = 8LL * 1024 * 1024;   // per-b stride in scores/P
    const long long ss_lo = 1024LL * 1024;       // per-head stride
    const long long sv_hi = 8LL * 131072;        // per-b stride in vT
    const long long sv_lo = 131072LL;            // per-head stride in vT

    // 0) one-time weight transposes (fp32 -> fp16, N x K) and Er copy
    transpose_f2h<<<dim3(96, 16),  dim3(32, 8)>>>(W_qkv,  3072, wq, 1024);
    transpose_f2h<<<dim3(32, 16),  dim3(32, 8)>>>(W_o,    1024, wo, 1024);
    transpose_f2h<<<dim3(128, 16), dim3(32, 8)>>>(W_fc,   4096, wf, 1024);
    transpose_f2h<<<dim3(32, 64),  dim3(32, 8)>>>(W_proj, 1024, wp, 4096);
    copy_f2h<<<128, 256>>>((const float4*)Er, er, 32768);

    // 1) LN1 -> fp16
    ln_kernel<<<8192, 256>>>(x, ln1_g, ln1_b, ln);

    // 2) QKV = ln @ W_qkv + b_qkv  (8192 x 3072 x 1024) -> fp16
    gemm_f16<<<dim3(24, 64, 1), 256, SMEM_DYN>>>(
        ln, 1024, 0, 0, wq, 1024, 0, 0, qkv, 3072, 0, 0,
        3072, 1024, b_qkv, nullptr, 1, 0, 1);

    // 2b) vT[bh] = v^T (128 x 1024 per head), fp16
    transpose_h2h<<<dim3(4, 16, 64), dim3(32, 8)>>>(
        qkv + 2048, sq_hi, sq_lo, 3072, vt, sv_hi, sv_lo, 1024);

    // 3) QEr[bh] = q @ Er^T  (batched 64, anti-tri skip) -> fp16
    gemm_f16<<<dim3(8, 8, 64), 256, SMEM_DYN>>>(
        qkv, 3072, sq_hi, sq_lo, er, 128, 0, 0, qer, 1024, ss_hi, ss_lo,
        1024, 128, nullptr, nullptr, 0, 2, 1);

    // 4) S[bh] = q @ k^T + skew(QEr)  (batched 64, lower-tri only) -> fp16
    gemm_f16<<<dim3(8, 8, 64), 256, SMEM_DYN>>>(
        qkv, 3072, sq_hi, sq_lo, qkv + 1024, 3072, sq_hi, sq_lo, sc, 1024, ss_hi, ss_lo,
        1024, 128, nullptr, qer, 4, 1, 1);

    // 5) P = causal softmax(S / sqrt(hs)) -> fp16
    softmax_kernel<<<dim3(1024, 64), 256>>>(sc, pb);

    // 6) y[bh] = P @ v  (batched 64, causal K bound) -> fp16
    gemm_f16<<<dim3(1, 8, 64), 256, SMEM_DYN>>>(
        pb, 1024, ss_hi, ss_lo, vt, 1024, sv_hi, sv_lo,
        yb, 1024, 1024LL * 1024, 128,
        128, 1024, nullptr, nullptr, 0, 3, 1);

    // 7) x1 = x + y @ W_o + b_o  (8192 x 1024 x 1024) -> d_out fp32
    gemm_f16<<<dim3(8, 64, 1), 256, SMEM_DYN>>>(
        yb, 1024, 0, 0, wo, 1024, 0, 0, out, 1024, 0, 0,
        1024, 1024, b_o, x, 3, 0, 0);

    // 8) LN2 -> fp16
    ln_kernel<<<8192, 256>>>(out, ln2_g, ln2_b, ln);

    // 9) h = gelu(ln @ W_fc + b_fc)  (8192 x 4096 x 1024) -> fp16
    gemm_f16<<<dim3(32, 64, 1), 256, SMEM_DYN>>>(
        ln, 1024, 0, 0, wf, 1024, 0, 0, hb, 4096, 0, 0,
        4096, 1024, b_fc, nullptr, 2, 0, 1);

    // 10) out = x1 + h @ W_proj + b_proj  (8192 x 1024 x 4096) -> fp32
    gemm_f16<<<dim3(8, 64, 1), 256, SMEM_DYN>>>(
        hb, 4096, 0, 0, wp, 4096, 0, 0, out, 1024, 0, 0,
        1024, 4096, b_proj, out, 3, 0, 0);
}

// round 14
// speedup vs baseline: 1.0322x; 1.0322x over previous
#include <cuda_runtime.h>
#include <cuda_fp16.h>
#include <math.h>
#include <stdint.h>

// Problem constants: B=8, L=1024, D=1024, F=4096, nh=8, hs=128, M=B*L=8192

// fp16 scratch
__device__ __half g_scores[67108864];  // 64*1024*1024  S (fp16, incl. Srel)
__device__ __half g_qer[67108864];     // 64*1024*1024  QEr (fp16)
__device__ __half g_ln[8388608];       // LN output
__device__ __half g_qkv[25165824];     // QKV
__device__ __half g_p[67108864];       // softmax P
__device__ __half g_y[8388608];        // attn out
__device__ __half g_hh[33554432];      // MLP hidden
__device__ __half g_wq[3145728];       // W_qkv^T  (3072 x 1024)
__device__ __half g_wo[1048576];       // W_o^T    (1024 x 1024)
__device__ __half g_wf[4194304];       // W_fc^T   (4096 x 1024)
__device__ __half g_wp[4194304];       // W_proj^T (1024 x 4096)
__device__ __half g_vt[8388608];       // v^T per head (64 x 128 x 1024)
__device__ __half g_er[131072];        // Er (1024 x 128)

__device__ __forceinline__ uint32_t smem_u32(const void* p) {
    uint32_t a;
    asm("{ .reg .u64 t; cvta.to.shared.u64 t, %1; cvt.u32.u64 %0, t; }" : "=r"(a) : "l"(p));
    return a;
}
__device__ __forceinline__ void cpa16(uint32_t dst, const void* src) {
    asm volatile("cp.async.cg.shared.global [%0], [%1], 16;\n" :: "r"(dst), "l"(src));
}
#define CPA_COMMIT() asm volatile("cp.async.commit_group;\n" ::: "memory")
#define CPA_WAIT2()  asm volatile("cp.async.wait_group 2;\n" ::: "memory")

__device__ __forceinline__ void ldsm4(uint32_t& r0, uint32_t& r1, uint32_t& r2, uint32_t& r3,
                                      uint32_t addr) {
    asm volatile("ldmatrix.sync.aligned.m8n8.x4.shared.b16 {%0,%1,%2,%3}, [%4];"
                 : "=r"(r0), "=r"(r1), "=r"(r2), "=r"(r3) : "r"(addr));
}
__device__ __forceinline__ void mma_f16(float c[4], const uint32_t a[4],
                                        uint32_t b0, uint32_t b1) {
    asm volatile(
        "mma.sync.aligned.m16n8k16.row.col.f32.f16.f16.f32 "
        "{%0,%1,%2,%3}, {%4,%5,%6,%7}, {%8,%9}, {%0,%1,%2,%3};"
        : "+f"(c[0]), "+f"(c[1]), "+f"(c[2]), "+f"(c[3])
        : "r"(a[0]), "r"(a[1]), "r"(a[2]), "r"(a[3]), "r"(b0), "r"(b1));
}

// ---------------------------------------------------------------------------
// fp16 mma.sync GEMM: C[MxN] = A[MxK] * Bt[NxK]^T, A/Bt fp16 K-major.
// Block tile 128x128, k-step 32, 4-stage cp.async (wait_group 2).
// 8 warps (2m x 4n), warp tile 64x32, 2 CTAs/SM.
// Batched via blockIdx.z: hi=z>>3, lo=z&7.
// epilogue: 0=none, 1=+bias, 2=+bias+GELU, 3=+bias+residual(fp32),
//           4=+skewed rel bias: C[r][cb] += Eh[r][cb - r + 1023] (Eh fp16 = resid arg)
// tri: 0=full, 1=lower-tri skip, 2=anti-tri skip,
//      3=causal K bound with reversed m0 order (heavy tiles scheduled first)
// half_out: 1 -> C is __half, else float
// ---------------------------------------------------------------------------
__global__ void __launch_bounds__(256, 2)
gemm_f16(const __half* __restrict__ A, int lda, long long sAhi, long long sAlo,
         const __half* __restrict__ Bt, int ldb, long long sBhi, long long sBlo,
         void* __restrict__ Cv, int ldc, long long sChi, long long sClo,
         int N, int K,
         const float* __restrict__ bias, const void* __restrict__ resid,
         int epilogue, int tri, int half_out)
{
    const int n0 = blockIdx.x * 128;
    // tri==3: reverse m-order so the heaviest (largest kmax) tiles launch first
    const int m0 = (tri == 3)
        ? (int)(gridDim.y - 1 - blockIdx.y) * 128
        : blockIdx.y * 128;
    if (tri == 1 && n0 > m0) return;
    if (tri == 2 && (m0 + n0) < (N - 255)) return;
    const int kmax = (tri == 3) ? min(K, m0 + 128) : K;
    const int ns = kmax >> 5;   // k-tiles of 32 (>= 4 for all calls)

    const int z = blockIdx.z, hi = z >> 3, lo = z & 7;
    A  += hi * sAhi + lo * sAlo;
    Bt += hi * sBhi + lo * sBlo;
    const long long coff = hi * sChi + lo * sClo;

    extern __shared__ __align__(16) char smem[];
    const uint32_t sbase = smem_u32(smem);

    const int tid  = threadIdx.x;
    const int lane = tid & 31;
    const int warp = tid >> 5;
    const int g  = lane >> 2;
    const int tg = lane & 3;
    const int wm = (warp >> 2) * 64;
    const int wn = (warp & 3) * 32;

    // staging: row = tid>>1 (0..127), chunks c0=(tid&1)*2, c0+1 (16B of 8 halves)
    const int srow = tid >> 1;
    const int c0   = (tid & 1) * 2;
    const uint32_t dA = (uint32_t)(srow * 80 + c0 * 16);
    const __half* Ap = A + (size_t)(m0 + srow) * lda + c0 * 8;
    const __half* Bp = Bt + (size_t)(n0 + srow) * ldb + c0 * 8;

    // ldmatrix lane addresses
    const uint32_t lmA = sbase +         (uint32_t)((wm + (lane & 15)) * 80 + (lane >> 4) * 16);
    const uint32_t lmB = sbase + 10240 + (uint32_t)((wn + (lane & 15)) * 80 + (lane >> 4) * 16);

#define STAGE(s_, p_) do { \
        const uint32_t bb_ = sbase + (uint32_t)(p_) * 20480u; \
        const __half* ga_ = Ap + ((s_) << 5); \
        const __half* gb_ = Bp + ((s_) << 5); \
        cpa16(bb_ + dA, ga_); \
        cpa16(bb_ + dA + 16, ga_ + 8); \
        cpa16(bb_ + 10240 + dA, gb_); \
        cpa16(bb_ + 10240 + dA + 16, gb_ + 8); \
    } while (0)

    float acc[4][4][4] = {};

    STAGE(0, 0); CPA_COMMIT();
    STAGE(1, 1); CPA_COMMIT();
    STAGE(2, 2); CPA_COMMIT();

    int p = 0;
    for (int s = 0; s < ns; s++) {
        CPA_WAIT2();
        __syncthreads();
        const uint32_t pb = (uint32_t)p * 20480u;
#pragma unroll
        for (int k16 = 0; k16 < 2; k16++) {
            uint32_t af[4][4], bf[4][2];
#pragma unroll
            for (int mt = 0; mt < 4; mt++)
                ldsm4(af[mt][0], af[mt][1], af[mt][2], af[mt][3],
                      lmA + pb + mt * 1280u + k16 * 32u);
#pragma unroll
            for (int ntp = 0; ntp < 2; ntp++)
                ldsm4(bf[ntp * 2][0], bf[ntp * 2 + 1][0], bf[ntp * 2][1], bf[ntp * 2 + 1][1],
                      lmB + pb + ntp * 1280u + k16 * 32u);
#pragma unroll
            for (int mt = 0; mt < 4; mt++)
#pragma unroll
                for (int nt = 0; nt < 4; nt++)
                    mma_f16(acc[mt][nt], af[mt], bf[nt][0], bf[nt][1]);
        }
        if (s + 3 < ns) {
            STAGE(s + 3, (p + 3) & 3);
        }
        CPA_COMMIT();
        p = (p + 1) & 3;
    }

    // Epilogue: acc[mt][nt] -> rows (r, r+8), cols (cb, cb+1)
#pragma unroll
    for (int mt = 0; mt < 4; mt++) {
#pragma unroll
        for (int nt = 0; nt < 4; nt++) {
            const int r  = m0 + wm + mt * 16 + g;
            const int cb = n0 + wn + nt * 8 + tg * 2;
            float b0 = 0.f, b1 = 0.f;
            if (epilogue == 1 || epilogue == 2 || epilogue == 3) {
                b0 = bias[cb]; b1 = bias[cb + 1];
            }
            float o00 = acc[mt][nt][0] + b0, o01 = acc[mt][nt][1] + b1;
            float o10 = acc[mt][nt][2] + b0, o11 = acc[mt][nt][3] + b1;
            const size_t i0 = (size_t)coff + (size_t)r * ldc + cb;
            const size_t i1 = (size_t)coff + (size_t)(r + 8) * ldc + cb;
            if (epilogue == 2) {
                o00 *= normcdff(o00); o01 *= normcdff(o01);
                o10 *= normcdff(o10); o11 *= normcdff(o11);
            } else if (epilogue == 3) {
                const float* rf = (const float*)resid;
                const float2 r0 = *(const float2*)(rf + i0);
                const float2 r1 = *(const float2*)(rf + i1);
                o00 += r0.x; o01 += r0.y; o10 += r1.x; o11 += r1.y;
            } else if (epilogue == 4) {
                // skewed relative bias (fp16 source): Eh[row][col - row + 1023]
                const __half* Eh = (const __half*)resid;
                const __half* E0 = Eh + (size_t)coff + (size_t)r * ldc + (cb - r + 1023);
                const __half* E1 = Eh + (size_t)coff + (size_t)(r + 8) * ldc + (cb - (r + 8) + 1023);
                o00 += __half2float(E0[0]); o01 += __half2float(E0[1]);
                o10 += __half2float(E1[0]); o11 += __half2float(E1[1]);
            }
            if (half_out) {
                *(__half2*)((__half*)Cv + i0) = __floats2half2_rn(o00, o01);
                *(__half2*)((__half*)Cv + i1) = __floats2half2_rn(o10, o11);
            } else {
                *(float2*)((float*)Cv + i0) = make_float2(o00, o01);
                *(float2*)((float*)Cv + i1) = make_float2(o10, o11);
            }
        }
    }
#undef STAGE
}

// ---------------------------------------------------------------------------
// Transpose fp32 -> fp16, coalesced __half2 writes.
// grid: (in_cols/32, in_rows/64), block (32, 8)
// ---------------------------------------------------------------------------
__global__ void __launch_bounds__(256)
transpose_f2h(const float* __restrict__ in, int ldi,
              __half* __restrict__ out, int ldo)
{
    __shared__ float t[64][33];
    const int c0 = blockIdx.x * 32, r0 = blockIdx.y * 64;
    const int x = threadIdx.x, y = threadIdx.y;
#pragma unroll
    for (int i = 0; i < 64; i += 8)
        t[y + i][x] = in[(size_t)(r0 + y + i) * ldi + c0 + x];
    __syncthreads();
#pragma unroll
    for (int i = 0; i < 32; i += 8) {
        const int orow = c0 + y + i;
        const __half2 v = __floats2half2_rn(t[2 * x][y + i], t[2 * x + 1][y + i]);
        *(__half2*)(out + (size_t)orow * ldo + r0 + 2 * x) = v;
    }
}

// Transpose fp16 -> fp16 (batched, for vT), coalesced __half2 writes.
__global__ void __launch_bounds__(256)
transpose_h2h(const __half* __restrict__ in, long long sIhi, long long sIlo, int ldi,
              __half* __restrict__ out, long long sOhi, long long sOlo, int ldo)
{
    __shared__ __half t[64][33];
    const int z = blockIdx.z, hi = z >> 3, lo = z & 7;
    in  += hi * sIhi + lo * sIlo;
    out += hi * sOhi + lo * sOlo;
    const int c0 = blockIdx.x * 32, r0 = blockIdx.y * 64;
    const int x = threadIdx.x, y = threadIdx.y;
#pragma unroll
    for (int i = 0; i < 64; i += 8)
        t[y + i][x] = in[(size_t)(r0 + y + i) * ldi + c0 + x];
    __syncthreads();
#pragma unroll
    for (int i = 0; i < 32; i += 8) {
        const int orow = c0 + y + i;
        __half2 v;
        v.x = t[2 * x][y + i];
        v.y = t[2 * x + 1][y + i];
        *(__half2*)(out + (size_t)orow * ldo + r0 + 2 * x) = v;
    }
}

__global__ void __launch_bounds__(256)
copy_f2h(const float4* __restrict__ in, __half* __restrict__ out, int n4)
{
    const int i = blockIdx.x * 256 + threadIdx.x;
    if (i < n4) {
        const float4 v = in[i];
        *(__half2*)(out + i * 4)     = __floats2half2_rn(v.x, v.y);
        *(__half2*)(out + i * 4 + 2) = __floats2half2_rn(v.z, v.w);
    }
}

// ---------------------------------------------------------------------------
// LayerNorm (rows of 1024), fp32 in -> fp16 out.
// ---------------------------------------------------------------------------
__global__ void __launch_bounds__(256)
ln_kernel(const float* __restrict__ x, const float* __restrict__ g,
          const float* __restrict__ b, __half* __restrict__ out)
{
    const int row = blockIdx.x;
    const int tid = threadIdx.x;
    const float4 xv = ((const float4*)(x + (size_t)row * 1024))[tid];

    float s  = xv.x + xv.y + xv.z + xv.w;
    float ss = xv.x * xv.x + xv.y * xv.y + xv.z * xv.z + xv.w * xv.w;
#pragma unroll
    for (int o = 16; o; o >>= 1) {
        s  += __shfl_xor_sync(0xffffffffu, s, o);
        ss += __shfl_xor_sync(0xffffffffu, ss, o);
    }
    __shared__ float sm[16];
    if ((tid & 31) == 0) { sm[tid >> 5] = s; sm[8 + (tid >> 5)] = ss; }
    __syncthreads();
    float S = 0.f, SS = 0.f;
#pragma unroll
    for (int i = 0; i < 8; i++) { S += sm[i]; SS += sm[8 + i]; }
    const float mu  = S * (1.f / 1024.f);
    const float var = SS * (1.f / 1024.f) - mu * mu;
    const float rs  = rsqrtf(var + 1e-5f);

    const float4 gv = ((const float4*)g)[tid];
    const float4 bv = ((const float4*)b)[tid];
    __half* orow = out + (size_t)row * 1024 + tid * 4;
    *(__half2*)(orow)     = __floats2half2_rn((xv.x - mu) * rs * gv.x + bv.x,
                                              (xv.y - mu) * rs * gv.y + bv.y);
    *(__half2*)(orow + 2) = __floats2half2_rn((xv.z - mu) * rs * gv.z + bv.z,
                                              (xv.w - mu) * rs * gv.w + bv.w);
}

// ---------------------------------------------------------------------------
// Causal softmax: S (fp16, incl. skewed rel bias) -> P fp16.
// Writes only up to the causal tile boundary kend = round_up(q+1, 128).
// ---------------------------------------------------------------------------
__global__ void __launch_bounds__(256)
softmax_kernel(const __half* __restrict__ S, __half* __restrict__ P)
{
    const int q  = blockIdx.x;
    const int bh = blockIdx.y;
    const size_t base = ((size_t)bh * 1024 + q) * 1024;
    const int tid = threadIdx.x;
    const float scale = 0.08838834764831845f;  // 1/sqrt(128)
    const int kend = ((q >> 7) + 1) << 7;

    float v[4];
    float mx = -3.4e38f;
#pragma unroll
    for (int i = 0; i < 4; i++) {
        const int k = tid + i * 256;
        float val = -3.4e38f;
        if (k <= q) val = __half2float(S[base + k]) * scale;
        v[i] = val;
        mx = fmaxf(mx, val);
    }
#pragma unroll
    for (int o = 16; o; o >>= 1) mx = fmaxf(mx, __shfl_xor_sync(0xffffffffu, mx, o));
    __shared__ float red[8];
    if ((tid & 31) == 0) red[tid >> 5] = mx;
    __syncthreads();
    float m2 = red[0];
#pragma unroll
    for (int i = 1; i < 8; i++) m2 = fmaxf(m2, red[i]);
    __syncthreads();

    float sum = 0.f;
#pragma unroll
    for (int i = 0; i < 4; i++) {
        const float e = (v[i] > -1e37f) ? expf(v[i] - m2) : 0.f;
        v[i] = e;
        sum += e;
    }
#pragma unroll
    for (int o = 16; o; o >>= 1) sum += __shfl_xor_sync(0xffffffffu, sum, o);
    if ((tid & 31) == 0) red[tid >> 5] = sum;
    __syncthreads();
    float tot = 0.f;
#pragma unroll
    for (int i = 0; i < 8; i++) tot += red[i];
    const float inv = 1.f / tot;
#pragma unroll
    for (int i = 0; i < 4; i++) {
        const int k = tid + i * 256;
        if (k < kend) P[base + k] = __float2half_rn(v[i] * inv);
    }
}

// ---------------------------------------------------------------------------
extern "C" void kernel_launch(void* const* d_in, const int* in_sizes, int n_in,
                              void* d_out, int out_size)
{
    (void)in_sizes; (void)n_in; (void)out_size;
    const float* x      = (const float*)d_in[0];
    const float* W_qkv  = (const float*)d_in[1];
    const float* b_qkv  = (const float*)d_in[2];
    const float* W_o    = (const float*)d_in[3];
    const float* b_o    = (const float*)d_in[4];
    const float* Er     = (const float*)d_in[5];
    const float* ln1_g  = (const float*)d_in[6];
    const float* ln1_b  = (const float*)d_in[7];
    const float* ln2_g  = (const float*)d_in[8];
    const float* ln2_b  = (const float*)d_in[9];
    const float* W_fc   = (const float*)d_in[10];
    const float* b_fc   = (const float*)d_in[11];
    const float* W_proj = (const float*)d_in[12];
    const float* b_proj = (const float*)d_in[13];
    float* out = (float*)d_out;

    __half *sc, *qer, *ln, *qkv, *pb, *yb, *hb, *wq, *wo, *wf, *wp, *vt, *er;
    cudaGetSymbolAddress((void**)&sc,  g_scores);
    cudaGetSymbolAddress((void**)&qer, g_qer);
    cudaGetSymbolAddress((void**)&ln,  g_ln);
    cudaGetSymbolAddress((void**)&qkv, g_qkv);
    cudaGetSymbolAddress((void**)&pb,  g_p);
    cudaGetSymbolAddress((void**)&yb,  g_y);
    cudaGetSymbolAddress((void**)&hb,  g_hh);
    cudaGetSymbolAddress((void**)&wq,  g_wq);
    cudaGetSymbolAddress((void**)&wo,  g_wo);
    cudaGetSymbolAddress((void**)&wf,  g_wf);
    cudaGetSymbolAddress((void**)&wp,  g_wp);
    cudaGetSymbolAddress((void**)&vt,  g_vt);
    cudaGetSymbolAddress((void**)&er,  g_er);

    const int SMEM_DYN = 4 * 20480;   // 80 KB, 4 stages
    cudaFuncSetAttribute(gemm_f16, cudaFuncAttributeMaxDynamicSharedMemorySize, SMEM_DYN);

    const long long sq_hi = 1024LL * 3072;      // per-b stride in qkv (halves)
    const long long sq_lo = 128LL;               // per-head stride in qkv
    const long long ss_hi = 8LL * 1024 * 1024;   // per-b stride in scores/P
    const long long ss_lo = 1024LL * 1024;       // per-head stride
    const long long sv_hi = 8LL * 131072;        // per-b stride in vT
    const long long sv_lo = 131072LL;            // per-head stride in vT

    // Launch order chosen so ncu (-s 5 -c 1) profiles the S-GEMM (launch #5).
    // 0) LN1 -> fp16
    ln_kernel<<<8192, 256>>>(x, ln1_g, ln1_b, ln);
    // 1) W_qkv^T (needed by QKV)
    transpose_f2h<<<dim3(96, 16),  dim3(32, 8)>>>(W_qkv,  3072, wq, 1024);
    // 2) Er copy (needed by QEr)
    copy_f2h<<<128, 256>>>((const float4*)Er, er, 32768);
    // 3) QKV = ln @ W_qkv + b_qkv  (8192 x 3072 x 1024) -> fp16
    gemm_f16<<<dim3(24, 64, 1), 256, SMEM_DYN>>>(
        ln, 1024, 0, 0, wq, 1024, 0, 0, qkv, 3072, 0, 0,
        3072, 1024, b_qkv, nullptr, 1, 0, 1);
    // 4) QEr[bh] = q @ Er^T  (batched 64, anti-tri skip) -> fp16
    gemm_f16<<<dim3(8, 8, 64), 256, SMEM_DYN>>>(
        qkv, 3072, sq_hi, sq_lo, er, 128, 0, 0, qer, 1024, ss_hi, ss_lo,
        1024, 128, nullptr, nullptr, 0, 2, 1);
    // 5) S[bh] = q @ k^T + skew(QEr)  (batched 64, lower-tri only) -> fp16
    gemm_f16<<<dim3(8, 8, 64), 256, SMEM_DYN>>>(
        qkv, 3072, sq_hi, sq_lo, qkv + 1024, 3072, sq_hi, sq_lo, sc, 1024, ss_hi, ss_lo,
        1024, 128, nullptr, qer, 4, 1, 1);
    // 6) vT[bh] = v^T (128 x 1024 per head), fp16
    transpose_h2h<<<dim3(4, 16, 64), dim3(32, 8)>>>(
        qkv + 2048, sq_hi, sq_lo, 3072, vt, sv_hi, sv_lo, 1024);
    // 7) P = causal softmax(S / sqrt(hs)) -> fp16
    softmax_kernel<<<dim3(1024, 64), 256>>>(sc, pb);
    // 8) y[bh] = P @ v  (batched 64, causal K bound, heavy tiles first) -> fp16
    gemm_f16<<<dim3(1, 8, 64), 256, SMEM_DYN>>>(
        pb, 1024, ss_hi, ss_lo, vt, 1024, sv_hi, sv_lo,
        yb, 1024, 1024LL * 1024, 128,
        128, 1024, nullptr, nullptr, 0, 3, 1);
    // 9) W_o^T
    transpose_f2h<<<dim3(32, 16),  dim3(32, 8)>>>(W_o, 1024, wo, 1024);
    // 10) x1 = x + y @ W_o + b_o  (8192 x 1024 x 1024) -> d_out fp32
    gemm_f16<<<dim3(8, 64, 1), 256, SMEM_DYN>>>(
        yb, 1024, 0, 0, wo, 1024, 0, 0, out, 1024, 0, 0,
        1024, 1024, b_o, x, 3, 0, 0);
    // 11) LN2 -> fp16
    ln_kernel<<<8192, 256>>>(out, ln2_g, ln2_b, ln);
    // 12) W_fc^T
    transpose_f2h<<<dim3(128, 16), dim3(32, 8)>>>(W_fc, 4096, wf, 1024);
    // 13) h = gelu(ln @ W_fc + b_fc)  (8192 x 4096 x 1024) -> fp16
    gemm_f16<<<dim3(32, 64, 1), 256, SMEM_DYN>>>(
        ln, 1024, 0, 0, wf, 1024, 0, 0, hb, 4096, 0, 0,
        4096, 1024, b_fc, nullptr, 2, 0, 1);
    // 14) W_proj^T
    transpose_f2h<<<dim3(32, 64),  dim3(32, 8)>>>(W_proj, 1024, wp, 4096);
    // 15) out = x1 + h @ W_proj + b_proj  (8192 x 1024 x 4096) -> fp32
    gemm_f16<<<dim3(8, 64, 1), 256, SMEM_DYN>>>(
        hb, 4096, 0, 0, wp, 4096, 0, 0, out, 1024, 0, 0,
        1024, 4096, b_proj, out, 3, 0, 0);
}